// round 10
// baseline (speedup 1.0000x reference)
#include <cuda_runtime.h>
#include <cuda_fp16.h>
#include <cstdint>

#define B_ 8
#define T_ 2048
#define C_ 1024
#define H_ 128

// Scratch (device globals: allocation-free rule)
__device__ __half g_Qh[B_ * T_ * H_];       // fp16, pre-scaled 1/32
__device__ __half g_Kh[B_ * T_ * H_];
__device__ __half g_Vt[B_ * T_ * H_];       // V transposed [b][h][t]
__device__ __half g_Wh[3][H_ * C_];         // fp16, transposed [z][h][k]
__device__ float  g_Op[2][B_ * T_ * H_];    // split-K partial O
__device__ float  g_Ml[2][B_ * T_];
__device__ float  g_Ll[2][B_ * T_];

// ---------------------------------------------------------------------------
// helpers
// ---------------------------------------------------------------------------
__device__ __forceinline__ void mma_f16(float* c, const uint32_t* a,
                                        uint32_t b0, uint32_t b1) {
    asm volatile(
        "mma.sync.aligned.m16n8k16.row.col.f32.f16.f16.f32 "
        "{%0,%1,%2,%3}, {%4,%5,%6,%7}, {%8,%9}, {%0,%1,%2,%3};"
        : "+f"(c[0]), "+f"(c[1]), "+f"(c[2]), "+f"(c[3])
        : "r"(a[0]), "r"(a[1]), "r"(a[2]), "r"(a[3]), "r"(b0), "r"(b1));
}

__device__ __forceinline__ uint32_t pack_h2(float lo, float hi) {
    __half2 h = __float22half2_rn(make_float2(lo, hi));
    return *reinterpret_cast<uint32_t*>(&h);
}

__device__ __forceinline__ void cp16(void* smem_dst, const void* gmem_src) {
    uint32_t s = (uint32_t)__cvta_generic_to_shared(smem_dst);
    asm volatile("cp.async.cg.shared.global [%0], [%1], 16;" :: "r"(s), "l"(gmem_src));
}
__device__ __forceinline__ void cp_commit() { asm volatile("cp.async.commit_group;"); }
__device__ __forceinline__ void cp_wait0()  { asm volatile("cp.async.wait_group 0;"); }
__device__ __forceinline__ void cp_wait1()  { asm volatile("cp.async.wait_group 1;"); }

// ---------------------------------------------------------------------------
// Kernel 0: W -> fp16, transposed to [z][h][k]
// ---------------------------------------------------------------------------
__global__ __launch_bounds__(256) void conv_wT(const float* __restrict__ Wq,
                                               const float* __restrict__ Wk,
                                               const float* __restrict__ Wv)
{
    __shared__ float tile[32][33];
    const int z = blockIdx.z;
    const float* W = (z == 0) ? Wq : (z == 1) ? Wk : Wv;   // [k][h]
    const int k0 = blockIdx.x * 32, h0 = blockIdx.y * 32;
    const int tid = threadIdx.x;
    #pragma unroll
    for (int p = 0; p < 4; p++) {
        int idx = tid + 256 * p;
        int kk = idx >> 5, hh = idx & 31;
        tile[kk][hh] = W[(k0 + kk) * H_ + h0 + hh];
    }
    __syncthreads();
    #pragma unroll
    for (int p = 0; p < 4; p++) {
        int idx = tid + 256 * p;
        int hh = idx >> 5, kk = idx & 31;
        g_Wh[z][(h0 + hh) * C_ + k0 + kk] = __float2half_rn(tile[kk][hh]);
    }
}

// ---------------------------------------------------------------------------
// Kernel 1: FUSED QKV projection, fp16 mma, 3-stage cp.async pipeline.
// Block 128 x 384, 512 thr = 16 warps (4m x 4n), warp 32x96, K-tile 32.
// A-frags converted fp32->fp16 directly at register load (no cvt pass).
// Epilogue writes Q/K normally and V TRANSPOSED (via smem) to g_Vt.
// Buffer: raw X 128x36f (18432B) + W fp16 384x40h (30720B) = 49152B. x3.
// ---------------------------------------------------------------------------
#define QRAW_STR 36          // floats per raw X row (144B, 2-way-conflict ok)
#define QB_OFF   18432
#define QBUF     49152
#define QKV_SMEM_BYTES (3 * QBUF)

__global__ __launch_bounds__(512, 1) void qkvf(const float* __restrict__ X)
{
    extern __shared__ char smc[];
    const __half* Wh = &g_Wh[0][0];

    const int tid  = threadIdx.x;
    const int lane = tid & 31;
    const int warp = tid >> 5;
    const int wm   = (warp & 3) * 32;
    const int wn   = (warp >> 2) * 96;
    const int row0 = blockIdx.x * 128;
    const int g    = lane >> 2;
    const int q4   = lane & 3;

    float acc[2][12][4];
    #pragma unroll
    for (int mt = 0; mt < 2; mt++)
        #pragma unroll
        for (int nt = 0; nt < 12; nt++)
            #pragma unroll
            for (int i = 0; i < 4; i++) acc[mt][nt][i] = 0.f;

    auto issue = [&](int kt) {
        char* base = smc + (kt % 3) * QBUF;
        int k0 = kt * 32;
        // X raw fp32: 128 rows x 8 cp16, 2/thread
        #pragma unroll
        for (int p = 0; p < 2; p++) {
            int fid = tid + 512 * p;
            int r = fid >> 3, c16 = fid & 7;
            cp16(base + r * 144 + c16 * 16,
                 X + (size_t)(row0 + r) * C_ + k0 + c16 * 4);
        }
        // W fp16: 384 rows x 4 cp16, 3/thread
        #pragma unroll
        for (int p = 0; p < 3; p++) {
            int fid = tid + 512 * p;
            int r = fid >> 2, c16 = fid & 3;
            cp16(base + QB_OFF + r * 80 + c16 * 16,
                 Wh + (size_t)r * C_ + k0 + c16 * 8);
        }
    };

    issue(0); cp_commit();
    issue(1); cp_commit();

    for (int kt = 0; kt < 32; kt++) {
        if (kt + 1 < 32) cp_wait1(); else cp_wait0();   // tile kt landed
        __syncthreads();
        if (kt + 2 < 32) { issue(kt + 2); cp_commit(); }

        const char* base = smc + (kt % 3) * QBUF;
        const float*    raw = (const float*)base;
        const uint32_t* Bu  = (const uint32_t*)(base + QB_OFF);

        #pragma unroll
        for (int s = 0; s < 2; s++) {
            uint32_t a[2][4];
            #pragma unroll
            for (int mt = 0; mt < 2; mt++) {
                int r = wm + mt * 16 + g;
                float2 v0 = *(const float2*)(raw + r * QRAW_STR + 16 * s + 2 * q4);
                float2 v1 = *(const float2*)(raw + (r + 8) * QRAW_STR + 16 * s + 2 * q4);
                float2 v2 = *(const float2*)(raw + r * QRAW_STR + 16 * s + 8 + 2 * q4);
                float2 v3 = *(const float2*)(raw + (r + 8) * QRAW_STR + 16 * s + 8 + 2 * q4);
                a[mt][0] = pack_h2(v0.x, v0.y);
                a[mt][1] = pack_h2(v1.x, v1.y);
                a[mt][2] = pack_h2(v2.x, v2.y);
                a[mt][3] = pack_h2(v3.x, v3.y);
            }
            #pragma unroll
            for (int nt = 0; nt < 12; nt++) {
                int n = wn + nt * 8 + g;
                uint32_t b0 = Bu[n * 20 + 8 * s + q4];
                uint32_t b1 = Bu[n * 20 + 8 * s + 4 + q4];
                mma_f16(acc[0][nt], a[0], b0, b1);
                mma_f16(acc[1][nt], a[1], b0, b1);
            }
        }
    }

    // ---- epilogue ----
    __syncthreads();                       // all mma reads done; smem reusable
    __half* Vsm = (__half*)smc;            // 128 x 136 halfs (34816B < QBUF)

    #pragma unroll
    for (int mt = 0; mt < 2; mt++) {
        int rl = wm + mt * 16 + g;         // local row
        int rg = row0 + rl;
        #pragma unroll
        for (int nt = 0; nt < 12; nt++) {
            int nt8 = wn + nt * 8;
            int z = nt8 >> 7;
            if (z < 2) {
                int h0 = (nt8 & 127) + 2 * q4;
                __half* out = (z == 0) ? g_Qh : g_Kh;
                float osc = (z == 0) ? 0.03125f : 1.0f;
                *(uint32_t*)(out + (size_t)rg * H_ + h0) =
                    pack_h2(acc[mt][nt][0] * osc, acc[mt][nt][1] * osc);
                *(uint32_t*)(out + (size_t)(rg + 8) * H_ + h0) =
                    pack_h2(acc[mt][nt][2] * osc, acc[mt][nt][3] * osc);
            } else {
                int h = (nt8 - 256) + 2 * q4;
                *(uint32_t*)(Vsm + rl * 136 + h) =
                    pack_h2(acc[mt][nt][0], acc[mt][nt][1]);
                *(uint32_t*)(Vsm + (rl + 8) * 136 + h) =
                    pack_h2(acc[mt][nt][2], acc[mt][nt][3]);
            }
        }
    }
    __syncthreads();

    // transposed V write: thread -> (h = tid>>2, t-chunk = (tid&3)*32)
    {
        int h   = tid >> 2;
        int sub = tid & 3;
        int bb  = row0 >> 11;
        int t0  = row0 & (T_ - 1);
        __half tmp[32];
        #pragma unroll
        for (int j = 0; j < 32; j++)
            tmp[j] = Vsm[(sub * 32 + j) * 136 + h];
        __half* dst = g_Vt + ((size_t)bb * H_ + h) * T_ + t0 + sub * 32;
        #pragma unroll
        for (int i = 0; i < 4; i++)
            *(uint4*)(dst + i * 8) = *(uint4*)(tmp + i * 8);
    }
}

// ---------------------------------------------------------------------------
// Kernel 2: split-K causal flash attention, fp16 mma, 3-stage K/V pipeline,
// one __syncthreads per k-iteration.
// smem: K[3][64][136]h + Vt[3][128][72]h + P[128][72]h
// ---------------------------------------------------------------------------
#define KOFF  0
#define KBUF  17408     // 64*272
#define VOFF  52224     // 3*KBUF
#define VBUF  18432     // 128*144
#define POFF  107520    // VOFF + 3*VBUF
#define ATTN_SMEM_BYTES 125952

__global__ __launch_bounds__(256, 1) void attn_part(void)
{
    extern __shared__ char smc[];

    const int c    = blockIdx.x;
    const int qt   = 15 - (c >> 4);
    const int b    = (c >> 1) & 7;
    const int half = c & 1;
    const int k0   = half ? (qt + 1) : 0;
    const int k1   = half ? (2 * qt + 2) : (qt + 1);

    const int tid  = threadIdx.x;
    const int lane = tid & 31;
    const int w    = tid >> 5;
    const int g    = lane >> 2;
    const int q4   = lane & 3;

    uint32_t qa[8][4];
    {
        const uint32_t* Qg = (const uint32_t*)g_Qh +
            ((size_t)b * T_ + (size_t)qt * 128 + w * 16) * (H_ / 2);
        #pragma unroll
        for (int ks = 0; ks < 8; ks++) {
            qa[ks][0] = Qg[g * 64 + 8 * ks + q4];
            qa[ks][1] = Qg[(g + 8) * 64 + 8 * ks + q4];
            qa[ks][2] = Qg[g * 64 + 8 * ks + 4 + q4];
            qa[ks][3] = Qg[(g + 8) * 64 + 8 * ks + 4 + q4];
        }
    }

    float m_run[2] = {-1e30f, -1e30f};
    float l_run[2] = {0.f, 0.f};
    float o[16][4];
    #pragma unroll
    for (int nt = 0; nt < 16; nt++)
        #pragma unroll
        for (int i = 0; i < 4; i++) o[nt][i] = 0.f;

    const int prow = w * 16 + g;

    auto issue = [&](int kt) {
        int buf = kt % 3;
        char* Kd = smc + KOFF + buf * KBUF;
        char* Vd = smc + VOFF + buf * VBUF;
        const __half* Kg = g_Kh + ((size_t)b * T_ + (size_t)kt * 64) * H_;
        const __half* Vg = g_Vt + (size_t)b * H_ * T_ + (size_t)kt * 64;
        #pragma unroll
        for (int p = 0; p < 4; p++) {
            int fid = tid + 256 * p;
            int r = fid >> 4, c16 = fid & 15;
            cp16(Kd + r * 272 + c16 * 16, Kg + r * H_ + c16 * 8);
        }
        #pragma unroll
        for (int p = 0; p < 4; p++) {
            int fid = tid + 256 * p;
            int h = fid >> 3, c16 = fid & 7;
            cp16(Vd + h * 144 + c16 * 16, Vg + (size_t)h * T_ + c16 * 8);
        }
    };

    issue(k0); cp_commit();
    if (k0 + 1 < k1) { issue(k0 + 1); cp_commit(); }

    for (int kt = k0; kt < k1; kt++) {
        if (kt + 1 < k1) cp_wait1(); else cp_wait0();
        __syncthreads();
        if (kt + 2 < k1) { issue(kt + 2); cp_commit(); }

        const uint32_t* Ku = (const uint32_t*)(smc + KOFF + (kt % 3) * KBUF);
        const uint32_t* Vu = (const uint32_t*)(smc + VOFF + (kt % 3) * VBUF);

        const int rel = qt * 128 + w * 16 - kt * 64;
        const bool fully_masked = (rel < -15);

        if (!fully_masked) {
            float s[8][4];
            #pragma unroll
            for (int nt = 0; nt < 8; nt++)
                #pragma unroll
                for (int i = 0; i < 4; i++) s[nt][i] = 0.f;

            #pragma unroll
            for (int ks = 0; ks < 8; ks++) {
                #pragma unroll
                for (int nt = 0; nt < 8; nt++) {
                    uint32_t b0 = Ku[(nt * 8 + g) * 68 + 8 * ks + q4];
                    uint32_t b1 = Ku[(nt * 8 + g) * 68 + 8 * ks + 4 + q4];
                    mma_f16(s[nt], qa[ks], b0, b1);
                }
            }

            if (rel < 64) {
                #pragma unroll
                for (int nt = 0; nt < 8; nt++) {
                    int c0 = nt * 8 + 2 * q4;
                    if (c0     > rel + g)     s[nt][0] = -1e30f;
                    if (c0 + 1 > rel + g)     s[nt][1] = -1e30f;
                    if (c0     > rel + g + 8) s[nt][2] = -1e30f;
                    if (c0 + 1 > rel + g + 8) s[nt][3] = -1e30f;
                }
            }

            #pragma unroll
            for (int h = 0; h < 2; h++) {
                float mt = -1e30f;
                #pragma unroll
                for (int nt = 0; nt < 8; nt++)
                    mt = fmaxf(mt, fmaxf(s[nt][2 * h], s[nt][2 * h + 1]));
                mt = fmaxf(mt, __shfl_xor_sync(0xffffffffu, mt, 1));
                mt = fmaxf(mt, __shfl_xor_sync(0xffffffffu, mt, 2));
                float mn = fmaxf(m_run[h], mt);
                float f  = __expf(m_run[h] - mn);
                m_run[h] = mn;
                float rs = 0.f;
                #pragma unroll
                for (int nt = 0; nt < 8; nt++) {
                    s[nt][2 * h]     = __expf(s[nt][2 * h] - mn);
                    s[nt][2 * h + 1] = __expf(s[nt][2 * h + 1] - mn);
                    rs += s[nt][2 * h] + s[nt][2 * h + 1];
                }
                rs += __shfl_xor_sync(0xffffffffu, rs, 1);
                rs += __shfl_xor_sync(0xffffffffu, rs, 2);
                l_run[h] = l_run[h] * f + rs;
                #pragma unroll
                for (int nt = 0; nt < 16; nt++) {
                    o[nt][2 * h]     *= f;
                    o[nt][2 * h + 1] *= f;
                }
            }

            __half* Ph = (__half*)(smc + POFF);
            #pragma unroll
            for (int nt = 0; nt < 8; nt++) {
                int c0 = nt * 8 + 2 * q4;
                *(uint32_t*)(Ph + prow * 72 + c0)       = pack_h2(s[nt][0], s[nt][1]);
                *(uint32_t*)(Ph + (prow + 8) * 72 + c0) = pack_h2(s[nt][2], s[nt][3]);
            }
            __syncwarp();

            const uint32_t* Pu = (const uint32_t*)(smc + POFF);
            #pragma unroll
            for (int ks = 0; ks < 4; ks++) {
                uint32_t a[4];
                a[0] = Pu[prow * 36 + 8 * ks + q4];
                a[1] = Pu[(prow + 8) * 36 + 8 * ks + q4];
                a[2] = Pu[prow * 36 + 8 * ks + 4 + q4];
                a[3] = Pu[(prow + 8) * 36 + 8 * ks + 4 + q4];
                #pragma unroll
                for (int nt = 0; nt < 16; nt++) {
                    uint32_t b0 = Vu[(nt * 8 + g) * 36 + 8 * ks + q4];
                    uint32_t b1 = Vu[(nt * 8 + g) * 36 + 8 * ks + 4 + q4];
                    mma_f16(o[nt], a, b0, b1);
                }
            }
        }
    }

    size_t rowg = (size_t)b * T_ + (size_t)qt * 128 + prow;
    float* Op = &g_Op[half][0];
    #pragma unroll
    for (int nt = 0; nt < 16; nt++) {
        int cn = nt * 8 + 2 * q4;
        *(float2*)(Op + rowg * H_ + cn)       = make_float2(o[nt][0], o[nt][1]);
        *(float2*)(Op + (rowg + 8) * H_ + cn) = make_float2(o[nt][2], o[nt][3]);
    }
    if (q4 == 0) {
        g_Ml[half][rowg]     = m_run[0];
        g_Ml[half][rowg + 8] = m_run[1];
        g_Ll[half][rowg]     = l_run[0];
        g_Ll[half][rowg + 8] = l_run[1];
    }
}

// ---------------------------------------------------------------------------
// Kernel 3: merge split-K partials (unchanged).
// ---------------------------------------------------------------------------
__global__ __launch_bounds__(256) void attn_merge(float* __restrict__ out)
{
    int gid = blockIdx.x * 256 + threadIdx.x;
    int row = gid >> 3;
    int c0  = (gid & 7) * 16;

    float m0 = g_Ml[0][row], m1 = g_Ml[1][row];
    float l0 = g_Ll[0][row], l1 = g_Ll[1][row];
    float M  = fmaxf(m0, m1);
    float a0 = __expf(m0 - M);
    float a1 = __expf(m1 - M);
    float inv = 1.f / (l0 * a0 + l1 * a1);
    a0 *= inv; a1 *= inv;

    const float4* O0 = (const float4*)(&g_Op[0][0] + (size_t)row * H_ + c0);
    const float4* O1 = (const float4*)(&g_Op[1][0] + (size_t)row * H_ + c0);
    float4* dst = (float4*)(out + (size_t)row * H_ + c0);
    #pragma unroll
    for (int i = 0; i < 4; i++) {
        float4 u = O0[i], v = O1[i];
        float4 r;
        r.x = u.x * a0 + v.x * a1;
        r.y = u.y * a0 + v.y * a1;
        r.z = u.z * a0 + v.z * a1;
        r.w = u.w * a0 + v.w * a1;
        dst[i] = r;
    }
}

// ---------------------------------------------------------------------------
extern "C" void kernel_launch(void* const* d_in, const int* in_sizes, int n_in,
                              void* d_out, int out_size)
{
    const float* X  = (const float*)d_in[0];
    const float* Wq = (const float*)d_in[1];
    const float* Wk = (const float*)d_in[2];
    const float* Wv = (const float*)d_in[3];
    float* out = (float*)d_out;
    (void)in_sizes; (void)n_in; (void)out_size;

    static int smem_set = 0;
    if (!smem_set) {
        cudaFuncSetAttribute(qkvf,
                             cudaFuncAttributeMaxDynamicSharedMemorySize,
                             QKV_SMEM_BYTES);
        cudaFuncSetAttribute(attn_part,
                             cudaFuncAttributeMaxDynamicSharedMemorySize,
                             ATTN_SMEM_BYTES);
        smem_set = 1;
    }

    conv_wT<<<dim3(C_ / 32, H_ / 32, 3), 256>>>(Wq, Wk, Wv);
    qkvf<<<T_ * B_ / 128, 512, QKV_SMEM_BYTES>>>(X);
    attn_part<<<256, 256, ATTN_SMEM_BYTES>>>();
    attn_merge<<<B_ * T_ * 8 / 256, 256>>>(out);
}

// round 11
// speedup vs baseline: 1.0040x; 1.0040x over previous
#include <cuda_runtime.h>
#include <cuda_fp16.h>
#include <cstdint>

#define B_ 8
#define T_ 2048
#define C_ 1024
#define H_ 128

// Scratch (device globals: allocation-free rule)
__device__ __half g_Qh[B_ * T_ * H_];       // fp16, pre-scaled 1/32
__device__ __half g_Kh[B_ * T_ * H_];
__device__ __half g_Vt[B_ * T_ * H_];       // V transposed [b][h][t]
__device__ __half g_Wh[3][H_ * C_];         // fp16, transposed [z][h][k]
__device__ float  g_Op[2][B_ * T_ * H_];    // split-K partial O
__device__ float  g_Ml[2][B_ * T_];
__device__ float  g_Ll[2][B_ * T_];

// ---------------------------------------------------------------------------
// helpers
// ---------------------------------------------------------------------------
__device__ __forceinline__ void mma_f16(float* c, const uint32_t* a,
                                        uint32_t b0, uint32_t b1) {
    asm volatile(
        "mma.sync.aligned.m16n8k16.row.col.f32.f16.f16.f32 "
        "{%0,%1,%2,%3}, {%4,%5,%6,%7}, {%8,%9}, {%0,%1,%2,%3};"
        : "+f"(c[0]), "+f"(c[1]), "+f"(c[2]), "+f"(c[3])
        : "r"(a[0]), "r"(a[1]), "r"(a[2]), "r"(a[3]), "r"(b0), "r"(b1));
}

__device__ __forceinline__ uint32_t pack_h2(float lo, float hi) {
    __half2 h = __float22half2_rn(make_float2(lo, hi));
    return *reinterpret_cast<uint32_t*>(&h);
}

__device__ __forceinline__ void cp16(void* smem_dst, const void* gmem_src) {
    uint32_t s = (uint32_t)__cvta_generic_to_shared(smem_dst);
    asm volatile("cp.async.cg.shared.global [%0], [%1], 16;" :: "r"(s), "l"(gmem_src));
}
__device__ __forceinline__ void cp_commit() { asm volatile("cp.async.commit_group;"); }
__device__ __forceinline__ void cp_wait0()  { asm volatile("cp.async.wait_group 0;"); }
__device__ __forceinline__ void cp_wait1()  { asm volatile("cp.async.wait_group 1;"); }

// ---------------------------------------------------------------------------
// Kernel 0: W -> fp16, transposed to [z][h][k]
// ---------------------------------------------------------------------------
__global__ __launch_bounds__(256) void conv_wT(const float* __restrict__ Wq,
                                               const float* __restrict__ Wk,
                                               const float* __restrict__ Wv)
{
    __shared__ float tile[32][33];
    const int z = blockIdx.z;
    const float* W = (z == 0) ? Wq : (z == 1) ? Wk : Wv;   // [k][h]
    const int k0 = blockIdx.x * 32, h0 = blockIdx.y * 32;
    const int tid = threadIdx.x;
    #pragma unroll
    for (int p = 0; p < 4; p++) {
        int idx = tid + 256 * p;
        int kk = idx >> 5, hh = idx & 31;
        tile[kk][hh] = W[(k0 + kk) * H_ + h0 + hh];
    }
    __syncthreads();
    #pragma unroll
    for (int p = 0; p < 4; p++) {
        int idx = tid + 256 * p;
        int hh = idx >> 5, kk = idx & 31;
        g_Wh[z][(h0 + hh) * C_ + k0 + kk] = __float2half_rn(tile[kk][hh]);
    }
}

// ---------------------------------------------------------------------------
// Kernel 1: FUSED QKV projection, fp16 mma, 3-STAGE cp.async pipeline with
// the cheap cvtA pass (R9 conversion + R10 pipeline depth).
// Block 128 x 384, 512 thr = 16 warps (4m x 4n), warp 32x96, K-tile 32.
// Per stage: raw X (128x36 f32) | A fp16 (128x40 h) | W fp16 (384x40 h).
// Epilogue writes Q/K normally and V TRANSPOSED (via smem) to g_Vt.
// ---------------------------------------------------------------------------
#define QRAW_OFF 0
#define QA_OFF   18432          // 128*36*4
#define QB_OFF   28672          // QA_OFF + 128*40*2
#define QBUF     59392          // QB_OFF + 384*40*2
#define QKV_SMEM_BYTES (3 * QBUF)

__global__ __launch_bounds__(512, 1) void qkvf(const float* __restrict__ X)
{
    extern __shared__ char smc[];
    const __half* Wh = &g_Wh[0][0];

    const int tid  = threadIdx.x;
    const int lane = tid & 31;
    const int warp = tid >> 5;
    const int wm   = (warp & 3) * 32;
    const int wn   = (warp >> 2) * 96;
    const int row0 = blockIdx.x * 128;
    const int g    = lane >> 2;
    const int q4   = lane & 3;

    float acc[2][12][4];
    #pragma unroll
    for (int mt = 0; mt < 2; mt++)
        #pragma unroll
        for (int nt = 0; nt < 12; nt++)
            #pragma unroll
            for (int i = 0; i < 4; i++) acc[mt][nt][i] = 0.f;

    auto issue = [&](int kt) {
        char* base = smc + (kt % 3) * QBUF;
        int k0 = kt * 32;
        // X raw fp32: 128 rows x 8 cp16, 2/thread
        #pragma unroll
        for (int p = 0; p < 2; p++) {
            int fid = tid + 512 * p;
            int r = fid >> 3, c16 = fid & 7;
            cp16(base + QRAW_OFF + r * 144 + c16 * 16,
                 X + (size_t)(row0 + r) * C_ + k0 + c16 * 4);
        }
        // W fp16: 384 rows x 4 cp16, 3/thread
        #pragma unroll
        for (int p = 0; p < 3; p++) {
            int fid = tid + 512 * p;
            int r = fid >> 2, c16 = fid & 3;
            cp16(base + QB_OFF + r * 80 + c16 * 16,
                 Wh + (size_t)r * C_ + k0 + c16 * 8);
        }
    };

    // convert raw(kt) -> fp16 A(kt); 4 half2 per thread
    auto cvtA = [&](int kt) {
        char* base = smc + (kt % 3) * QBUF;
        const float* raw = (const float*)(base + QRAW_OFF);
        __half* Ah = (__half*)(base + QA_OFF);
        #pragma unroll
        for (int p = 0; p < 4; p++) {
            int j = tid + 512 * p;          // half2 id, 0..2047
            int m = j >> 4, kh = j & 15;
            float2 v = *(const float2*)(raw + m * 36 + 2 * kh);
            *(__half2*)(Ah + m * 40 + 2 * kh) = __float22half2_rn(v);
        }
    };

    issue(0); cp_commit();
    issue(1); cp_commit();

    for (int kt = 0; kt < 32; kt++) {
        if (kt + 1 < 32) cp_wait1(); else cp_wait0();   // tile kt landed
        __syncthreads();                                // landed data visible
        if (kt + 2 < 32) { issue(kt + 2); cp_commit(); }
        cvtA(kt);
        __syncthreads();                                // A(kt) visible

        const char* base = smc + (kt % 3) * QBUF;
        const uint32_t* Au = (const uint32_t*)(base + QA_OFF);
        const uint32_t* Bu = (const uint32_t*)(base + QB_OFF);

        #pragma unroll
        for (int s = 0; s < 2; s++) {
            uint32_t a[2][4];
            #pragma unroll
            for (int mt = 0; mt < 2; mt++) {
                int r = wm + mt * 16 + g;
                a[mt][0] = Au[r * 20 + 8 * s + q4];
                a[mt][1] = Au[(r + 8) * 20 + 8 * s + q4];
                a[mt][2] = Au[r * 20 + 8 * s + 4 + q4];
                a[mt][3] = Au[(r + 8) * 20 + 8 * s + 4 + q4];
            }
            #pragma unroll
            for (int nt = 0; nt < 12; nt++) {
                int n = wn + nt * 8 + g;
                uint32_t b0 = Bu[n * 20 + 8 * s + q4];
                uint32_t b1 = Bu[n * 20 + 8 * s + 4 + q4];
                mma_f16(acc[0][nt], a[0], b0, b1);
                mma_f16(acc[1][nt], a[1], b0, b1);
            }
        }
        // no trailing sync: next iter's wait+sync orders buffer reuse
        // (issue(kt+2) targets buffer (kt+2)%3, untouched by mma(kt))
        __syncthreads();
    }

    // ---- epilogue ----
    __half* Vsm = (__half*)smc;            // 128 x 136 halfs, overlays stage 0

    #pragma unroll
    for (int mt = 0; mt < 2; mt++) {
        int rl = wm + mt * 16 + g;
        int rg = row0 + rl;
        #pragma unroll
        for (int nt = 0; nt < 12; nt++) {
            int nt8 = wn + nt * 8;
            int z = nt8 >> 7;
            if (z < 2) {
                int h0 = (nt8 & 127) + 2 * q4;
                __half* out = (z == 0) ? g_Qh : g_Kh;
                float osc = (z == 0) ? 0.03125f : 1.0f;
                *(uint32_t*)(out + (size_t)rg * H_ + h0) =
                    pack_h2(acc[mt][nt][0] * osc, acc[mt][nt][1] * osc);
                *(uint32_t*)(out + (size_t)(rg + 8) * H_ + h0) =
                    pack_h2(acc[mt][nt][2] * osc, acc[mt][nt][3] * osc);
            } else {
                int h = (nt8 - 256) + 2 * q4;
                *(uint32_t*)(Vsm + rl * 136 + h) =
                    pack_h2(acc[mt][nt][0], acc[mt][nt][1]);
                *(uint32_t*)(Vsm + (rl + 8) * 136 + h) =
                    pack_h2(acc[mt][nt][2], acc[mt][nt][3]);
            }
        }
    }
    __syncthreads();

    // transposed V write: thread -> (h = tid>>2, t-chunk = (tid&3)*32)
    {
        int h   = tid >> 2;
        int sub = tid & 3;
        int bb  = row0 >> 11;
        int t0  = row0 & (T_ - 1);
        __half tmp[32];
        #pragma unroll
        for (int j = 0; j < 32; j++)
            tmp[j] = Vsm[(sub * 32 + j) * 136 + h];
        __half* dst = g_Vt + ((size_t)bb * H_ + h) * T_ + t0 + sub * 32;
        #pragma unroll
        for (int i = 0; i < 4; i++)
            *(uint4*)(dst + i * 8) = *(uint4*)(tmp + i * 8);
    }
}

// ---------------------------------------------------------------------------
// Kernel 2: split-K causal flash attention — byte-exact Round-9 version
// (2-stage K/V double buffer; measured 44us).
// smem: K[2][64][136]h + Vt[2][128][72]h + P[128][72]h
// ---------------------------------------------------------------------------
#define KOFF  0
#define KBUF  17408     // 64*272
#define VOFF  34816
#define VBUF  18432     // 128*144
#define POFF  71680
#define ATTN_SMEM_BYTES 90112

__global__ __launch_bounds__(256, 1) void attn_part(void)
{
    extern __shared__ char smc[];

    const int c    = blockIdx.x;
    const int qt   = 15 - (c >> 4);
    const int b    = (c >> 1) & 7;
    const int half = c & 1;
    const int k0   = half ? (qt + 1) : 0;
    const int k1   = half ? (2 * qt + 2) : (qt + 1);

    const int tid  = threadIdx.x;
    const int lane = tid & 31;
    const int w    = tid >> 5;
    const int g    = lane >> 2;
    const int q4   = lane & 3;

    uint32_t qa[8][4];
    {
        const uint32_t* Qg = (const uint32_t*)g_Qh +
            ((size_t)b * T_ + (size_t)qt * 128 + w * 16) * (H_ / 2);
        #pragma unroll
        for (int ks = 0; ks < 8; ks++) {
            qa[ks][0] = Qg[g * 64 + 8 * ks + q4];
            qa[ks][1] = Qg[(g + 8) * 64 + 8 * ks + q4];
            qa[ks][2] = Qg[g * 64 + 8 * ks + 4 + q4];
            qa[ks][3] = Qg[(g + 8) * 64 + 8 * ks + 4 + q4];
        }
    }

    float m_run[2] = {-1e30f, -1e30f};
    float l_run[2] = {0.f, 0.f};
    float o[16][4];
    #pragma unroll
    for (int nt = 0; nt < 16; nt++)
        #pragma unroll
        for (int i = 0; i < 4; i++) o[nt][i] = 0.f;

    const int prow = w * 16 + g;

    auto issue = [&](int kt) {
        int buf = kt & 1;
        char* Kd = smc + KOFF + buf * KBUF;
        char* Vd = smc + VOFF + buf * VBUF;
        const __half* Kg = g_Kh + ((size_t)b * T_ + (size_t)kt * 64) * H_;
        const __half* Vg = g_Vt + (size_t)b * H_ * T_ + (size_t)kt * 64;
        #pragma unroll
        for (int p = 0; p < 4; p++) {
            int fid = tid + 256 * p;
            int r = fid >> 4, c16 = fid & 15;
            cp16(Kd + r * 272 + c16 * 16, Kg + r * H_ + c16 * 8);
        }
        #pragma unroll
        for (int p = 0; p < 4; p++) {
            int fid = tid + 256 * p;
            int h = fid >> 3, c16 = fid & 7;
            cp16(Vd + h * 144 + c16 * 16, Vg + (size_t)h * T_ + c16 * 8);
        }
    };

    issue(k0);
    cp_commit();

    for (int kt = k0; kt < k1; kt++) {
        if (kt < k1 - 1) {
            issue(kt + 1);
            cp_commit();
            cp_wait1();
        } else {
            cp_wait0();
        }
        __syncthreads();

        const uint32_t* Ku = (const uint32_t*)(smc + KOFF + (kt & 1) * KBUF);
        const uint32_t* Vu = (const uint32_t*)(smc + VOFF + (kt & 1) * VBUF);

        const int rel = qt * 128 + w * 16 - kt * 64;
        const bool fully_masked = (rel < -15);

        if (!fully_masked) {
            float s[8][4];
            #pragma unroll
            for (int nt = 0; nt < 8; nt++)
                #pragma unroll
                for (int i = 0; i < 4; i++) s[nt][i] = 0.f;

            #pragma unroll
            for (int ks = 0; ks < 8; ks++) {
                #pragma unroll
                for (int nt = 0; nt < 8; nt++) {
                    uint32_t b0 = Ku[(nt * 8 + g) * 68 + 8 * ks + q4];
                    uint32_t b1 = Ku[(nt * 8 + g) * 68 + 8 * ks + 4 + q4];
                    mma_f16(s[nt], qa[ks], b0, b1);
                }
            }

            if (rel < 64) {
                #pragma unroll
                for (int nt = 0; nt < 8; nt++) {
                    int c0 = nt * 8 + 2 * q4;
                    if (c0     > rel + g)     s[nt][0] = -1e30f;
                    if (c0 + 1 > rel + g)     s[nt][1] = -1e30f;
                    if (c0     > rel + g + 8) s[nt][2] = -1e30f;
                    if (c0 + 1 > rel + g + 8) s[nt][3] = -1e30f;
                }
            }

            #pragma unroll
            for (int h = 0; h < 2; h++) {
                float mt = -1e30f;
                #pragma unroll
                for (int nt = 0; nt < 8; nt++)
                    mt = fmaxf(mt, fmaxf(s[nt][2 * h], s[nt][2 * h + 1]));
                mt = fmaxf(mt, __shfl_xor_sync(0xffffffffu, mt, 1));
                mt = fmaxf(mt, __shfl_xor_sync(0xffffffffu, mt, 2));
                float mn = fmaxf(m_run[h], mt);
                float f  = __expf(m_run[h] - mn);
                m_run[h] = mn;
                float rs = 0.f;
                #pragma unroll
                for (int nt = 0; nt < 8; nt++) {
                    s[nt][2 * h]     = __expf(s[nt][2 * h] - mn);
                    s[nt][2 * h + 1] = __expf(s[nt][2 * h + 1] - mn);
                    rs += s[nt][2 * h] + s[nt][2 * h + 1];
                }
                rs += __shfl_xor_sync(0xffffffffu, rs, 1);
                rs += __shfl_xor_sync(0xffffffffu, rs, 2);
                l_run[h] = l_run[h] * f + rs;
                #pragma unroll
                for (int nt = 0; nt < 16; nt++) {
                    o[nt][2 * h]     *= f;
                    o[nt][2 * h + 1] *= f;
                }
            }

            __half* Ph = (__half*)(smc + POFF);
            #pragma unroll
            for (int nt = 0; nt < 8; nt++) {
                int c0 = nt * 8 + 2 * q4;
                *(uint32_t*)(Ph + prow * 72 + c0)       = pack_h2(s[nt][0], s[nt][1]);
                *(uint32_t*)(Ph + (prow + 8) * 72 + c0) = pack_h2(s[nt][2], s[nt][3]);
            }
            __syncwarp();

            const uint32_t* Pu = (const uint32_t*)(smc + POFF);
            #pragma unroll
            for (int ks = 0; ks < 4; ks++) {
                uint32_t a[4];
                a[0] = Pu[prow * 36 + 8 * ks + q4];
                a[1] = Pu[(prow + 8) * 36 + 8 * ks + q4];
                a[2] = Pu[prow * 36 + 8 * ks + 4 + q4];
                a[3] = Pu[(prow + 8) * 36 + 8 * ks + 4 + q4];
                #pragma unroll
                for (int nt = 0; nt < 16; nt++) {
                    uint32_t b0 = Vu[(nt * 8 + g) * 36 + 8 * ks + q4];
                    uint32_t b1 = Vu[(nt * 8 + g) * 36 + 8 * ks + 4 + q4];
                    mma_f16(o[nt], a, b0, b1);
                }
            }
        }
        __syncthreads();
    }

    size_t rowg = (size_t)b * T_ + (size_t)qt * 128 + prow;
    float* Op = &g_Op[half][0];
    #pragma unroll
    for (int nt = 0; nt < 16; nt++) {
        int cn = nt * 8 + 2 * q4;
        *(float2*)(Op + rowg * H_ + cn)       = make_float2(o[nt][0], o[nt][1]);
        *(float2*)(Op + (rowg + 8) * H_ + cn) = make_float2(o[nt][2], o[nt][3]);
    }
    if (q4 == 0) {
        g_Ml[half][rowg]     = m_run[0];
        g_Ml[half][rowg + 8] = m_run[1];
        g_Ll[half][rowg]     = l_run[0];
        g_Ll[half][rowg + 8] = l_run[1];
    }
}

// ---------------------------------------------------------------------------
// Kernel 3: merge split-K partials (unchanged).
// ---------------------------------------------------------------------------
__global__ __launch_bounds__(256) void attn_merge(float* __restrict__ out)
{
    int gid = blockIdx.x * 256 + threadIdx.x;
    int row = gid >> 3;
    int c0  = (gid & 7) * 16;

    float m0 = g_Ml[0][row], m1 = g_Ml[1][row];
    float l0 = g_Ll[0][row], l1 = g_Ll[1][row];
    float M  = fmaxf(m0, m1);
    float a0 = __expf(m0 - M);
    float a1 = __expf(m1 - M);
    float inv = 1.f / (l0 * a0 + l1 * a1);
    a0 *= inv; a1 *= inv;

    const float4* O0 = (const float4*)(&g_Op[0][0] + (size_t)row * H_ + c0);
    const float4* O1 = (const float4*)(&g_Op[1][0] + (size_t)row * H_ + c0);
    float4* dst = (float4*)(out + (size_t)row * H_ + c0);
    #pragma unroll
    for (int i = 0; i < 4; i++) {
        float4 u = O0[i], v = O1[i];
        float4 r;
        r.x = u.x * a0 + v.x * a1;
        r.y = u.y * a0 + v.y * a1;
        r.z = u.z * a0 + v.z * a1;
        r.w = u.w * a0 + v.w * a1;
        dst[i] = r;
    }
}

// ---------------------------------------------------------------------------
extern "C" void kernel_launch(void* const* d_in, const int* in_sizes, int n_in,
                              void* d_out, int out_size)
{
    const float* X  = (const float*)d_in[0];
    const float* Wq = (const float*)d_in[1];
    const float* Wk = (const float*)d_in[2];
    const float* Wv = (const float*)d_in[3];
    float* out = (float*)d_out;
    (void)in_sizes; (void)n_in; (void)out_size;

    static int smem_set = 0;
    if (!smem_set) {
        cudaFuncSetAttribute(qkvf,
                             cudaFuncAttributeMaxDynamicSharedMemorySize,
                             QKV_SMEM_BYTES);
        cudaFuncSetAttribute(attn_part,
                             cudaFuncAttributeMaxDynamicSharedMemorySize,
                             ATTN_SMEM_BYTES);
        smem_set = 1;
    }

    conv_wT<<<dim3(C_ / 32, H_ / 32, 3), 256>>>(Wq, Wk, Wv);
    qkvf<<<T_ * B_ / 128, 512, QKV_SMEM_BYTES>>>(X);
    attn_part<<<256, 256, ATTN_SMEM_BYTES>>>();
    attn_merge<<<B_ * T_ * 8 / 256, 256>>>(out);
}